// round 1
// baseline (speedup 1.0000x reference)
#include <cuda_runtime.h>

// Problem constants (fixed shapes from reference setup_inputs)
#define BATCH   262144
#define NIN     128
#define NMID    512
#define NEXTRA  2
#define NCOLS   (NIN + NEXTRA)   // 130
#define GRID1   1024             // blocks in reduction pass
#define ROWS_PER_BLK (BATCH / GRID1)  // 256

// Scratch (device globals — no allocation allowed)
// g_partial layout: [129][GRID1] (transposed so stage-2 column sums are coalesced)
//   rows 0..127: weighted column sums of x; row 128: partial sums of w
__device__ float g_partial[(NIN + 1) * GRID1];
__device__ float g_o[NIN];

// ---------------------------------------------------------------------------
// Pass 1: per-block weighted column sums.  blockDim = 128 (one thread/column)
// ---------------------------------------------------------------------------
__global__ __launch_bounds__(128) void reduce_pass(const float* __restrict__ x,
                                                   const float* __restrict__ w) {
    const int c = threadIdx.x;        // column 0..127
    const int b = blockIdx.x;         // 0..GRID1-1
    const long r0 = (long)b * ROWS_PER_BLK;

    float acc  = 0.0f;
    float wacc = 0.0f;

    const float* xrow = x + r0 * NIN + c;
    const float* wp   = w + r0;

#pragma unroll 4
    for (int r = 0; r < ROWS_PER_BLK; ++r) {
        float wv = __ldg(wp + r);                 // broadcast load
        acc = fmaf(wv, __ldg(xrow + (long)r * NIN), acc);
        wacc += wv;
    }

    g_partial[c * GRID1 + b] = acc;
    if (c == 0) g_partial[NIN * GRID1 + b] = wacc;
}

// ---------------------------------------------------------------------------
// Middle: reduce partials, v = relu(W_in @ xbar), o = W_out @ v.  1 block.
// ---------------------------------------------------------------------------
__global__ __launch_bounds__(512) void mid_pass(const float* __restrict__ p,
                                                const float* __restrict__ W_in,
                                                const float* __restrict__ W_out) {
    __shared__ float colsum[NIN + 1];
    __shared__ float v[NMID];

    const int tid = threadIdx.x;  // 0..511

    if (tid < NIN + 1) {
        float s = 0.0f;
        const float* pp = g_partial + tid * GRID1;
#pragma unroll 8
        for (int b = 0; b < GRID1; ++b) s += pp[b];
        colsum[tid] = s;
    }
    __syncthreads();

    // v_m = relu( (W_in[m,0:128] . colsum[0:128]) / wsum + W_in[m,128]*p0 + W_in[m,129]*p1 )
    {
        const float inv_w = 1.0f / colsum[NIN];
        const float* wrow = W_in + (long)tid * NCOLS;
        float acc = 0.0f;
#pragma unroll 8
        for (int j = 0; j < NIN; ++j) acc = fmaf(wrow[j], colsum[j], acc);
        acc *= inv_w;
        acc = fmaf(wrow[NIN],     p[0], acc);
        acc = fmaf(wrow[NIN + 1], p[1], acc);
        v[tid] = fmaxf(acc, 0.0f);
    }
    __syncthreads();

    // o_c = W_out[c,:] . v   (second weighted average is identity)
    if (tid < NIN) {
        const float* wrow = W_out + (long)tid * NMID;
        float acc = 0.0f;
#pragma unroll 8
        for (int m = 0; m < NMID; ++m) acc = fmaf(wrow[m], v[m], acc);
        g_o[tid] = acc;
    }
}

// ---------------------------------------------------------------------------
// Pass 2: out = x + o (broadcast over rows), float4 vectorized grid-stride.
// ---------------------------------------------------------------------------
__global__ __launch_bounds__(256) void add_pass(const float* __restrict__ x,
                                                float* __restrict__ out) {
    __shared__ float4 o4[NIN / 4];     // 32 float4 = one row of o
    if (threadIdx.x < NIN / 4) {
        const float* o = g_o;
        o4[threadIdx.x] = reinterpret_cast<const float4*>(o)[threadIdx.x];
    }
    __syncthreads();

    const long total = (long)BATCH * NIN / 4;
    const long stride = (long)gridDim.x * blockDim.x;
    const float4* x4 = reinterpret_cast<const float4*>(x);
    float4* out4 = reinterpret_cast<float4*>(out);

    for (long i = (long)blockIdx.x * blockDim.x + threadIdx.x; i < total; i += stride) {
        float4 xv = x4[i];
        float4 ov = o4[i & (NIN / 4 - 1)];   // column group = i % 32 (row-major)
        xv.x += ov.x; xv.y += ov.y; xv.z += ov.z; xv.w += ov.w;
        out4[i] = xv;
    }
}

// ---------------------------------------------------------------------------
extern "C" void kernel_launch(void* const* d_in, const int* in_sizes, int n_in,
                              void* d_out, int out_size) {
    const float* x     = (const float*)d_in[0];   // [262144,128]
    const float* w     = (const float*)d_in[1];   // [262144,1]
    const float* p     = (const float*)d_in[2];   // [1,2]
    const float* W_in  = (const float*)d_in[3];   // [512,130]
    const float* W_out = (const float*)d_in[4];   // [128,512]
    float* out = (float*)d_out;                   // [262144,128]

    reduce_pass<<<GRID1, 128>>>(x, w);
    mid_pass<<<1, NMID>>>(p, W_in, W_out);
    add_pass<<<2048, 256>>>(x, out);
}

// round 2
// speedup vs baseline: 1.9383x; 1.9383x over previous
#include <cuda_runtime.h>

// Fixed shapes
#define BATCH   262144
#define NIN     128
#define NMID    512
#define NCOLS   130            // n_in + n_extra
#define GRID1   1024           // reduction blocks
#define ROWS_PER_BLK (BATCH / GRID1)   // 256
#define LANES   8              // warps per reduce block
#define ROWS_PER_LANE (ROWS_PER_BLK / LANES)  // 32

// Scratch (device globals; allocation is forbidden)
// g_partial: [129][GRID1]  (rows 0..127 = weighted col sums, row 128 = w sums)
__device__ float g_partial[(NIN + 1) * GRID1];
__device__ float g_o[NIN];

// ---------------------------------------------------------------------------
// Pass 1: weighted column sums. 256 threads = 8 warps; warp = one row (float4
// per lane, 128B coalesced). Warp `lane` owns rows lane, lane+8, ... (32 rows).
// ---------------------------------------------------------------------------
__global__ __launch_bounds__(256) void reduce_pass(const float* __restrict__ x,
                                                   const float* __restrict__ w) {
    const int tid  = threadIdx.x;
    const int cg   = tid & 31;        // column group 0..31 (float4)
    const int lane = tid >> 5;        // warp id 0..7
    const int b    = blockIdx.x;
    const long r0  = (long)b * ROWS_PER_BLK;

    const float4* x4 = reinterpret_cast<const float4*>(x);

    float4 acc = make_float4(0.f, 0.f, 0.f, 0.f);
    float wacc = 0.0f;

#pragma unroll
    for (int i = 0; i < ROWS_PER_LANE; ++i) {
        const long r = r0 + lane + i * LANES;
        float  wv = __ldg(w + r);                 // broadcast within warp
        float4 xv = __ldg(x4 + r * 32 + cg);
        acc.x = fmaf(wv, xv.x, acc.x);
        acc.y = fmaf(wv, xv.y, acc.y);
        acc.z = fmaf(wv, xv.z, acc.z);
        acc.w = fmaf(wv, xv.w, acc.w);
        wacc += wv;
    }

    __shared__ float s[LANES][NIN + 4];           // +4 pad: no bank conflicts
    __shared__ float sw[LANES];
    s[lane][cg * 4 + 0] = acc.x;
    s[lane][cg * 4 + 1] = acc.y;
    s[lane][cg * 4 + 2] = acc.z;
    s[lane][cg * 4 + 3] = acc.w;
    if (cg == 0) sw[lane] = wacc;                 // whole warp shares same wacc
    __syncthreads();

    if (tid < NIN) {
        float v = 0.0f;
#pragma unroll
        for (int l = 0; l < LANES; ++l) v += s[l][tid];
        g_partial[tid * GRID1 + b] = v;
    } else if (tid == NIN) {
        float v = 0.0f;
#pragma unroll
        for (int l = 0; l < LANES; ++l) v += sw[l];
        g_partial[NIN * GRID1 + b] = v;
    }
}

// ---------------------------------------------------------------------------
// Middle: reduce partials -> xbar, v = relu(W_in @ xbar), o = W_out @ v.
// One block, 576 threads (18 warps).
//   Phase A: 4 threads per column (516 threads), 256 partials each, MLP~16.
//   Phase B: warp-per-row GEMV over W_in (coalesced lane loads + shfl reduce).
//   Phase C: warp-per-row GEMV over W_out.
// ---------------------------------------------------------------------------
__global__ __launch_bounds__(576) void mid_pass(const float* __restrict__ p,
                                                const float* __restrict__ W_in,
                                                const float* __restrict__ W_out) {
    __shared__ float part[(NIN + 1) * 4];
    __shared__ float xbar[NCOLS];
    __shared__ float v[NMID];

    const int tid    = threadIdx.x;
    const int warpid = tid >> 5;
    const int lid    = tid & 31;

    // Phase A1: 4-way partial sums per column
    if (tid < (NIN + 1) * 4) {
        const int col = tid >> 2;
        const int k   = tid & 3;
        const float* pp = g_partial + col * GRID1;
        float s = 0.0f;
#pragma unroll 16
        for (int bi = k; bi < GRID1; bi += 4) s += pp[bi];
        part[tid] = s;
    }
    __syncthreads();

    // Phase A2: combine, build xbar
    if (tid < NIN + 1) {
        float cs = part[tid * 4] + part[tid * 4 + 1] + part[tid * 4 + 2] + part[tid * 4 + 3];
        part[tid] = cs;           // reuse slot: colsum
    }
    __syncthreads();
    if (tid < NIN) {
        xbar[tid] = part[tid] / part[NIN];
    } else if (tid == NIN) {
        xbar[NIN]     = __ldg(p + 0);
        xbar[NIN + 1] = __ldg(p + 1);
    }
    __syncthreads();

    // Phase B: v[r] = relu(W_in[r,:] . xbar), warp per row
    for (int r = warpid; r < NMID; r += 18) {
        const float* wrow = W_in + (long)r * NCOLS;
        float acc = 0.0f;
#pragma unroll
        for (int j = lid; j < NCOLS; j += 32) acc = fmaf(__ldg(wrow + j), xbar[j], acc);
#pragma unroll
        for (int off = 16; off > 0; off >>= 1)
            acc += __shfl_xor_sync(0xffffffffu, acc, off);
        if (lid == 0) v[r] = fmaxf(acc, 0.0f);
    }
    __syncthreads();

    // Phase C: g_o[c] = W_out[c,:] . v, warp per row (2nd weighted avg = identity)
    for (int c = warpid; c < NIN; c += 18) {
        const float* wrow = W_out + (long)c * NMID;
        float acc = 0.0f;
#pragma unroll
        for (int m = lid; m < NMID; m += 32) acc = fmaf(__ldg(wrow + m), v[m], acc);
#pragma unroll
        for (int off = 16; off > 0; off >>= 1)
            acc += __shfl_xor_sync(0xffffffffu, acc, off);
        if (lid == 0) g_o[c] = acc;
    }
}

// ---------------------------------------------------------------------------
// Pass 2: out = x + o. Exact-cover grid: 8192 blocks x 256 threads x 4 float4.
// Stride is a multiple of 32 float4 -> each thread's column group is fixed,
// so the broadcast row element lives in registers (loaded once).
// ---------------------------------------------------------------------------
#define ADD_BLOCKS 8192
#define ADD_STRIDE ((long)ADD_BLOCKS * 256)   // 2,097,152 float4 (mult of 32)

__global__ __launch_bounds__(256) void add_pass(const float* __restrict__ x,
                                                float* __restrict__ out) {
    const long base = (long)blockIdx.x * 256 + threadIdx.x;
    const float4 ov = __ldg(reinterpret_cast<const float4*>(g_o) + (threadIdx.x & 31));

    const float4* x4 = reinterpret_cast<const float4*>(x);
    float4* out4 = reinterpret_cast<float4*>(out);

    float4 a = __ldg(x4 + base + 0 * ADD_STRIDE);
    float4 b = __ldg(x4 + base + 1 * ADD_STRIDE);
    float4 c = __ldg(x4 + base + 2 * ADD_STRIDE);
    float4 d = __ldg(x4 + base + 3 * ADD_STRIDE);

    a.x += ov.x; a.y += ov.y; a.z += ov.z; a.w += ov.w;
    b.x += ov.x; b.y += ov.y; b.z += ov.z; b.w += ov.w;
    c.x += ov.x; c.y += ov.y; c.z += ov.z; c.w += ov.w;
    d.x += ov.x; d.y += ov.y; d.z += ov.z; d.w += ov.w;

    out4[base + 0 * ADD_STRIDE] = a;
    out4[base + 1 * ADD_STRIDE] = b;
    out4[base + 2 * ADD_STRIDE] = c;
    out4[base + 3 * ADD_STRIDE] = d;
}

// ---------------------------------------------------------------------------
extern "C" void kernel_launch(void* const* d_in, const int* in_sizes, int n_in,
                              void* d_out, int out_size) {
    const float* x     = (const float*)d_in[0];   // [262144,128]
    const float* w     = (const float*)d_in[1];   // [262144,1]
    const float* p     = (const float*)d_in[2];   // [1,2]
    const float* W_in  = (const float*)d_in[3];   // [512,130]
    const float* W_out = (const float*)d_in[4];   // [128,512]
    float* out = (float*)d_out;                   // [262144,128]

    reduce_pass<<<GRID1, 256>>>(x, w);
    mid_pass<<<1, 576>>>(p, W_in, W_out);
    add_pass<<<ADD_BLOCKS, 256>>>(x, out);
}

// round 3
// speedup vs baseline: 2.3715x; 1.2235x over previous
#include <cuda_runtime.h>

// Fixed shapes
#define BATCH   262144
#define NIN     128
#define NMID    512
#define NCOLS   130                      // n_in + n_extra
#define GRID1   1024                     // reduction blocks
#define ROWS_PER_BLK (BATCH / GRID1)     // 256

// Scratch (device globals; allocation forbidden)
__device__ __align__(16) float g_partial[(NIN + 1) * GRID1]; // [col][block]
__device__ __align__(16) float g_o[NIN];
__device__ float g_dummy[64 * 256];      // sink for W prefetch (never read)

// Total W elements for prefetch
#define NW_IN  (NMID * NCOLS)            // 66560
#define NW_OUT (NIN * NMID)              // 65536
#define NW_TOT (NW_IN + NW_OUT)          // 132096
#define PF_BLOCKS 64
#define PF_SLICE  (NW_TOT / PF_BLOCKS)   // 2064

// ---------------------------------------------------------------------------
// Pass 1: weighted column sums. 256 thr = 8 warps; warp owns 32 contiguous
// rows; 4 rows per iteration with one float4 w-load -> 5 independent loads
// per unrolled step. Last 64 blocks also prefetch W_in/W_out into L2.
// ---------------------------------------------------------------------------
__global__ __launch_bounds__(256) void reduce_pass(const float* __restrict__ x,
                                                   const float* __restrict__ w,
                                                   const float* __restrict__ W_in,
                                                   const float* __restrict__ W_out) {
    const int tid = threadIdx.x;
    const int cg  = tid & 31;            // float4 column group
    const int wp  = tid >> 5;            // warp 0..7
    const int b   = blockIdx.x;
    const long rbase = (long)b * ROWS_PER_BLK + (long)wp * 32;

    const float4* x4 = reinterpret_cast<const float4*>(x) + rbase * 32 + cg;
    const float4* w4 = reinterpret_cast<const float4*>(w) + (rbase >> 2);

    float4 acc0 = make_float4(0.f, 0.f, 0.f, 0.f);
    float4 acc1 = make_float4(0.f, 0.f, 0.f, 0.f);
    float  wacc = 0.0f;

#pragma unroll
    for (int i = 0; i < 8; ++i) {        // 4 rows per iter
        float4 wv = __ldg(w4 + i);
        float4 a  = __ldg(x4 + (4 * i + 0) * 32);
        float4 bb = __ldg(x4 + (4 * i + 1) * 32);
        float4 c  = __ldg(x4 + (4 * i + 2) * 32);
        float4 d  = __ldg(x4 + (4 * i + 3) * 32);
        acc0.x = fmaf(wv.x, a.x,  acc0.x); acc0.y = fmaf(wv.x, a.y,  acc0.y);
        acc0.z = fmaf(wv.x, a.z,  acc0.z); acc0.w = fmaf(wv.x, a.w,  acc0.w);
        acc1.x = fmaf(wv.y, bb.x, acc1.x); acc1.y = fmaf(wv.y, bb.y, acc1.y);
        acc1.z = fmaf(wv.y, bb.z, acc1.z); acc1.w = fmaf(wv.y, bb.w, acc1.w);
        acc0.x = fmaf(wv.z, c.x,  acc0.x); acc0.y = fmaf(wv.z, c.y,  acc0.y);
        acc0.z = fmaf(wv.z, c.z,  acc0.z); acc0.w = fmaf(wv.z, c.w,  acc0.w);
        acc1.x = fmaf(wv.w, d.x,  acc1.x); acc1.y = fmaf(wv.w, d.y,  acc1.y);
        acc1.z = fmaf(wv.w, d.z,  acc1.z); acc1.w = fmaf(wv.w, d.w,  acc1.w);
        wacc += (wv.x + wv.y) + (wv.z + wv.w);
    }
    acc0.x += acc1.x; acc0.y += acc1.y; acc0.z += acc1.z; acc0.w += acc1.w;

    __shared__ float s[8][NIN + 4];
    __shared__ float sw[8];
    s[wp][cg * 4 + 0] = acc0.x;
    s[wp][cg * 4 + 1] = acc0.y;
    s[wp][cg * 4 + 2] = acc0.z;
    s[wp][cg * 4 + 3] = acc0.w;
    if (cg == 0) sw[wp] = wacc;
    __syncthreads();

    if (tid < NIN) {
        float v = 0.0f;
#pragma unroll
        for (int l = 0; l < 8; ++l) v += s[l][tid];
        g_partial[tid * GRID1 + b] = v;
    } else if (tid == NIN) {
        float v = 0.0f;
#pragma unroll
        for (int l = 0; l < 8; ++l) v += sw[l];
        g_partial[NIN * GRID1 + b] = v;
    }

    // Tail blocks (scheduled last) warm W_in/W_out into L2 for mid_pass.
    if (b >= GRID1 - PF_BLOCKS) {
        const int sidx = b - (GRID1 - PF_BLOCKS);
        float dummy = 0.0f;
        for (int i = sidx * PF_SLICE + tid; i < (sidx + 1) * PF_SLICE; i += 256) {
            dummy += (i < NW_IN) ? __ldg(W_in + i) : __ldg(W_out + (i - NW_IN));
        }
        g_dummy[sidx * 256 + tid] = dummy;   // unique slot: deterministic
    }
}

// ---------------------------------------------------------------------------
// Middle kernel: colsum -> xbar; v = relu(W_in @ xbar); o = W_out @ v.
// One block, 1024 threads (32 warps). W is L2-warm from the prefetch.
// ---------------------------------------------------------------------------
__global__ __launch_bounds__(1024) void mid_pass(const float* __restrict__ p,
                                                 const float* __restrict__ W_in,
                                                 const float* __restrict__ W_out) {
    __shared__ float part[(NIN + 1) * 4];
    __shared__ float colsum[NIN + 1];
    __shared__ float xbar[NCOLS];
    __shared__ float v[NMID];

    const int tid    = threadIdx.x;
    const int warpid = tid >> 5;
    const int lid    = tid & 31;

    // Phase A: column sums of g_partial (float4, 4 threads per column)
    if (tid < (NIN + 1) * 4) {
        const int col = tid >> 2;
        const int k   = tid & 3;
        const float4* pp = reinterpret_cast<const float4*>(g_partial + col * GRID1);
        float4 s4 = make_float4(0.f, 0.f, 0.f, 0.f);
#pragma unroll 8
        for (int i = k; i < GRID1 / 4; i += 4) {
            float4 t = __ldg(pp + i);
            s4.x += t.x; s4.y += t.y; s4.z += t.z; s4.w += t.w;
        }
        part[tid] = (s4.x + s4.y) + (s4.z + s4.w);
    }
    __syncthreads();
    if (tid < NIN + 1)
        colsum[tid] = (part[tid * 4] + part[tid * 4 + 1]) + (part[tid * 4 + 2] + part[tid * 4 + 3]);
    __syncthreads();
    if (tid < NIN) {
        xbar[tid] = colsum[tid] / colsum[NIN];
    } else if (tid == NIN) {
        xbar[NIN]     = __ldg(p + 0);
        xbar[NIN + 1] = __ldg(p + 1);
    }
    __syncthreads();

    // Phase B: v[r] = relu(W_in[r,:] . xbar). 32 warps x 16 rows, 4 rows/step.
#pragma unroll
    for (int g = 0; g < 4; ++g) {
        const int r = warpid * 16 + g * 4;
        const float* w0 = W_in + (long)(r + 0) * NCOLS;
        const float* w1 = W_in + (long)(r + 1) * NCOLS;
        const float* w2 = W_in + (long)(r + 2) * NCOLS;
        const float* w3 = W_in + (long)(r + 3) * NCOLS;
        float a0 = 0.f, a1 = 0.f, a2 = 0.f, a3 = 0.f;
#pragma unroll
        for (int j = lid; j < NCOLS; j += 32) {
            const float xb = xbar[j];
            a0 = fmaf(__ldg(w0 + j), xb, a0);
            a1 = fmaf(__ldg(w1 + j), xb, a1);
            a2 = fmaf(__ldg(w2 + j), xb, a2);
            a3 = fmaf(__ldg(w3 + j), xb, a3);
        }
#pragma unroll
        for (int off = 16; off > 0; off >>= 1) {
            a0 += __shfl_xor_sync(0xffffffffu, a0, off);
            a1 += __shfl_xor_sync(0xffffffffu, a1, off);
            a2 += __shfl_xor_sync(0xffffffffu, a2, off);
            a3 += __shfl_xor_sync(0xffffffffu, a3, off);
        }
        if (lid == 0) {
            v[r + 0] = fmaxf(a0, 0.0f);
            v[r + 1] = fmaxf(a1, 0.0f);
            v[r + 2] = fmaxf(a2, 0.0f);
            v[r + 3] = fmaxf(a3, 0.0f);
        }
    }
    __syncthreads();

    // Phase C: g_o[c] = W_out[c,:] . v. 32 warps x 4 rows, 2 rows/step.
#pragma unroll
    for (int g = 0; g < 2; ++g) {
        const int c = warpid * 4 + g * 2;
        const float* w0 = W_out + (long)(c + 0) * NMID;
        const float* w1 = W_out + (long)(c + 1) * NMID;
        float a0 = 0.f, a1 = 0.f;
#pragma unroll
        for (int m = lid; m < NMID; m += 32) {
            const float vv = v[m];
            a0 = fmaf(__ldg(w0 + m), vv, a0);
            a1 = fmaf(__ldg(w1 + m), vv, a1);
        }
#pragma unroll
        for (int off = 16; off > 0; off >>= 1) {
            a0 += __shfl_xor_sync(0xffffffffu, a0, off);
            a1 += __shfl_xor_sync(0xffffffffu, a1, off);
        }
        if (lid == 0) {
            g_o[c + 0] = a0;
            g_o[c + 1] = a1;
        }
    }
}

// ---------------------------------------------------------------------------
// Pass 2: out = x + o. 2048 blocks x 256 thr x 16 float4 (exact cover).
// Blocks reversed so the L2-resident tail of x (from reduce_pass) is read
// first; __ldcs/__stcs keep the streams from evicting still-needed x lines.
// ---------------------------------------------------------------------------
#define ADD_BLOCKS   2048
#define F4_PER_BLOCK 4096                // 256 threads * 16

__global__ __launch_bounds__(256) void add_pass(const float* __restrict__ x,
                                                float* __restrict__ out) {
    const int  tid  = threadIdx.x;
    const long rb   = (long)(ADD_BLOCKS - 1 - blockIdx.x);
    const long base = rb * F4_PER_BLOCK + tid;

    const float4 ov = *(reinterpret_cast<const float4*>(g_o) + (tid & 31));
    const float4* x4 = reinterpret_cast<const float4*>(x);
    float4* o4p = reinterpret_cast<float4*>(out);

#pragma unroll
    for (int half = 0; half < 2; ++half) {
        float4 r[8];
#pragma unroll
        for (int k = 0; k < 8; ++k)
            r[k] = __ldcs(x4 + base + (long)(half * 8 + k) * 256);
#pragma unroll
        for (int k = 0; k < 8; ++k) {
            r[k].x += ov.x; r[k].y += ov.y; r[k].z += ov.z; r[k].w += ov.w;
            __stcs(o4p + base + (long)(half * 8 + k) * 256, r[k]);
        }
    }
}

// ---------------------------------------------------------------------------
extern "C" void kernel_launch(void* const* d_in, const int* in_sizes, int n_in,
                              void* d_out, int out_size) {
    const float* x     = (const float*)d_in[0];   // [262144,128]
    const float* w     = (const float*)d_in[1];   // [262144,1]
    const float* p     = (const float*)d_in[2];   // [1,2]
    const float* W_in  = (const float*)d_in[3];   // [512,130]
    const float* W_out = (const float*)d_in[4];   // [128,512]
    float* out = (float*)d_out;                   // [262144,128]

    reduce_pass<<<GRID1, 256>>>(x, w, W_in, W_out);
    mid_pass<<<1, 1024>>>(p, W_in, W_out);
    add_pass<<<ADD_BLOCKS, 256>>>(x, out);
}

// round 4
// speedup vs baseline: 2.4877x; 1.0490x over previous
#include <cuda_runtime.h>

// Fixed shapes
#define BATCH   262144
#define NIN     128
#define NMID    512
#define NCOLS   130                      // n_in + n_extra
#define GRID1   512                      // reduction blocks (single wave, headroom)
#define ROWS_PER_BLK (BATCH / GRID1)     // 512

// Scratch (device globals; allocation forbidden)
__device__ __align__(16) float g_partial[(NIN + 1) * GRID1]; // [col][block]
__device__ __align__(16) float g_o[NIN];

// ---------------------------------------------------------------------------
// Pass 1: weighted column sums. 256 thr = 8 warps; warp owns 64 contiguous
// rows; 4 rows per iteration with one float4 w-load (5 independent LDG.128
// per step). 512 blocks -> single wave even at ~48 regs.
// ---------------------------------------------------------------------------
__global__ __launch_bounds__(256) void reduce_pass(const float* __restrict__ x,
                                                   const float* __restrict__ w) {
    const int tid = threadIdx.x;
    const int cg  = tid & 31;            // float4 column group
    const int wp  = tid >> 5;            // warp 0..7
    const int b   = blockIdx.x;
    const long rbase = (long)b * ROWS_PER_BLK + (long)wp * 64;

    const float4* x4 = reinterpret_cast<const float4*>(x) + rbase * 32 + cg;
    const float4* w4 = reinterpret_cast<const float4*>(w) + (rbase >> 2);

    float4 acc0 = make_float4(0.f, 0.f, 0.f, 0.f);
    float4 acc1 = make_float4(0.f, 0.f, 0.f, 0.f);
    float  wacc = 0.0f;

#pragma unroll
    for (int i = 0; i < 16; ++i) {       // 4 rows per iter, 64 rows total
        float4 wv = __ldg(w4 + i);
        float4 a  = __ldg(x4 + (4 * i + 0) * 32);
        float4 bb = __ldg(x4 + (4 * i + 1) * 32);
        float4 c  = __ldg(x4 + (4 * i + 2) * 32);
        float4 d  = __ldg(x4 + (4 * i + 3) * 32);
        acc0.x = fmaf(wv.x, a.x,  acc0.x); acc0.y = fmaf(wv.x, a.y,  acc0.y);
        acc0.z = fmaf(wv.x, a.z,  acc0.z); acc0.w = fmaf(wv.x, a.w,  acc0.w);
        acc1.x = fmaf(wv.y, bb.x, acc1.x); acc1.y = fmaf(wv.y, bb.y, acc1.y);
        acc1.z = fmaf(wv.y, bb.z, acc1.z); acc1.w = fmaf(wv.y, bb.w, acc1.w);
        acc0.x = fmaf(wv.z, c.x,  acc0.x); acc0.y = fmaf(wv.z, c.y,  acc0.y);
        acc0.z = fmaf(wv.z, c.z,  acc0.z); acc0.w = fmaf(wv.z, c.w,  acc0.w);
        acc1.x = fmaf(wv.w, d.x,  acc1.x); acc1.y = fmaf(wv.w, d.y,  acc1.y);
        acc1.z = fmaf(wv.w, d.z,  acc1.z); acc1.w = fmaf(wv.w, d.w,  acc1.w);
        wacc += (wv.x + wv.y) + (wv.z + wv.w);
    }
    acc0.x += acc1.x; acc0.y += acc1.y; acc0.z += acc1.z; acc0.w += acc1.w;

    __shared__ float s[8][NIN + 4];
    __shared__ float sw[8];
    s[wp][cg * 4 + 0] = acc0.x;
    s[wp][cg * 4 + 1] = acc0.y;
    s[wp][cg * 4 + 2] = acc0.z;
    s[wp][cg * 4 + 3] = acc0.w;
    if (cg == 0) sw[wp] = wacc;
    __syncthreads();

    if (tid < NIN) {
        float v = 0.0f;
#pragma unroll
        for (int l = 0; l < 8; ++l) v += s[l][tid];
        g_partial[tid * GRID1 + b] = v;
    } else if (tid == NIN) {
        float v = 0.0f;
#pragma unroll
        for (int l = 0; l < 8; ++l) v += sw[l];
        g_partial[NIN * GRID1 + b] = v;
    }
}

// ---------------------------------------------------------------------------
// Middle kernel: colsum -> xbar; v = relu(W_in @ xbar); o = W_out @ v.
// One block, 1024 threads (32 warps).
// ---------------------------------------------------------------------------
__global__ __launch_bounds__(1024) void mid_pass(const float* __restrict__ p,
                                                 const float* __restrict__ W_in,
                                                 const float* __restrict__ W_out) {
    __shared__ float part[(NIN + 1) * 4];
    __shared__ float colsum[NIN + 1];
    __shared__ float xbar[NCOLS];
    __shared__ float v[NMID];

    const int tid    = threadIdx.x;
    const int warpid = tid >> 5;
    const int lid    = tid & 31;

    // Phase A: column sums of g_partial (float4, 4 threads per column)
    if (tid < (NIN + 1) * 4) {
        const int col = tid >> 2;
        const int k   = tid & 3;
        const float4* pp = reinterpret_cast<const float4*>(g_partial + col * GRID1);
        float4 s4 = make_float4(0.f, 0.f, 0.f, 0.f);
#pragma unroll 8
        for (int i = k; i < GRID1 / 4; i += 4) {
            float4 t = __ldg(pp + i);
            s4.x += t.x; s4.y += t.y; s4.z += t.z; s4.w += t.w;
        }
        part[tid] = (s4.x + s4.y) + (s4.z + s4.w);
    }
    __syncthreads();
    if (tid < NIN + 1)
        colsum[tid] = (part[tid * 4] + part[tid * 4 + 1]) + (part[tid * 4 + 2] + part[tid * 4 + 3]);
    __syncthreads();
    if (tid < NIN) {
        xbar[tid] = colsum[tid] / colsum[NIN];
    } else if (tid == NIN) {
        xbar[NIN]     = __ldg(p + 0);
        xbar[NIN + 1] = __ldg(p + 1);
    }
    __syncthreads();

    // Phase B: v[r] = relu(W_in[r,:] . xbar). 32 warps x 16 rows, 4 rows/step.
#pragma unroll
    for (int g = 0; g < 4; ++g) {
        const int r = warpid * 16 + g * 4;
        const float* w0 = W_in + (long)(r + 0) * NCOLS;
        const float* w1 = W_in + (long)(r + 1) * NCOLS;
        const float* w2 = W_in + (long)(r + 2) * NCOLS;
        const float* w3 = W_in + (long)(r + 3) * NCOLS;
        float a0 = 0.f, a1 = 0.f, a2 = 0.f, a3 = 0.f;
#pragma unroll
        for (int j = lid; j < NCOLS; j += 32) {
            const float xb = xbar[j];
            a0 = fmaf(__ldg(w0 + j), xb, a0);
            a1 = fmaf(__ldg(w1 + j), xb, a1);
            a2 = fmaf(__ldg(w2 + j), xb, a2);
            a3 = fmaf(__ldg(w3 + j), xb, a3);
        }
#pragma unroll
        for (int off = 16; off > 0; off >>= 1) {
            a0 += __shfl_xor_sync(0xffffffffu, a0, off);
            a1 += __shfl_xor_sync(0xffffffffu, a1, off);
            a2 += __shfl_xor_sync(0xffffffffu, a2, off);
            a3 += __shfl_xor_sync(0xffffffffu, a3, off);
        }
        if (lid == 0) {
            v[r + 0] = fmaxf(a0, 0.0f);
            v[r + 1] = fmaxf(a1, 0.0f);
            v[r + 2] = fmaxf(a2, 0.0f);
            v[r + 3] = fmaxf(a3, 0.0f);
        }
    }
    __syncthreads();

    // Phase C: g_o[c] = W_out[c,:] . v. 32 warps x 4 rows, 2 rows/step.
#pragma unroll
    for (int g = 0; g < 2; ++g) {
        const int c = warpid * 4 + g * 2;
        const float* w0 = W_out + (long)(c + 0) * NMID;
        const float* w1 = W_out + (long)(c + 1) * NMID;
        float a0 = 0.f, a1 = 0.f;
#pragma unroll
        for (int m = lid; m < NMID; m += 32) {
            const float vv = v[m];
            a0 = fmaf(__ldg(w0 + m), vv, a0);
            a1 = fmaf(__ldg(w1 + m), vv, a1);
        }
#pragma unroll
        for (int off = 16; off > 0; off >>= 1) {
            a0 += __shfl_xor_sync(0xffffffffu, a0, off);
            a1 += __shfl_xor_sync(0xffffffffu, a1, off);
        }
        if (lid == 0) {
            g_o[c + 0] = a0;
            g_o[c + 1] = a1;
        }
    }
}

// ---------------------------------------------------------------------------
// Pass 2: out = x + o. 4096 blocks x 256 thr x 8 float4 (exact cover, 32KB
// per block). Block remap: each reduce slice (256KB = 8 add-blocks) is read
// TAIL-FIRST across waves, so the most-recently-used (L2-resident) parts of x
// are consumed before anything evicts them. __ldcs marks x evict-first after
// its single use; __stcs keeps the out stream from displacing resident x.
// ---------------------------------------------------------------------------
#define ADD_BLOCKS   4096
#define F4_PER_BLOCK 2048                // 256 threads * 8

__global__ __launch_bounds__(256) void add_pass(const float* __restrict__ x,
                                                float* __restrict__ out) {
    const int tid = threadIdx.x;
    // remap: group g = beta/512 handles sub-block (7-g) of every 256KB slice
    const int beta  = blockIdx.x;
    const int slice = beta & 511;            // 0..511
    const int sub   = 7 - (beta >> 9);       // 7..0
    const long blk  = (long)slice * 8 + sub;
    const long base = blk * F4_PER_BLOCK + tid;

    const float4 ov = *(reinterpret_cast<const float4*>(g_o) + (tid & 31));
    const float4* x4 = reinterpret_cast<const float4*>(x);
    float4* o4p = reinterpret_cast<float4*>(out);

    float4 r[8];
#pragma unroll
    for (int k = 0; k < 8; ++k)
        r[k] = __ldcs(x4 + base + (long)k * 256);
#pragma unroll
    for (int k = 0; k < 8; ++k) {
        r[k].x += ov.x; r[k].y += ov.y; r[k].z += ov.z; r[k].w += ov.w;
        __stcs(o4p + base + (long)k * 256, r[k]);
    }
}

// ---------------------------------------------------------------------------
extern "C" void kernel_launch(void* const* d_in, const int* in_sizes, int n_in,
                              void* d_out, int out_size) {
    const float* x     = (const float*)d_in[0];   // [262144,128]
    const float* w     = (const float*)d_in[1];   // [262144,1]
    const float* p     = (const float*)d_in[2];   // [1,2]
    const float* W_in  = (const float*)d_in[3];   // [512,130]
    const float* W_out = (const float*)d_in[4];   // [128,512]
    float* out = (float*)d_out;                   // [262144,128]

    reduce_pass<<<GRID1, 256>>>(x, w);
    mid_pass<<<1, 1024>>>(p, W_in, W_out);
    add_pass<<<ADD_BLOCKS, 256>>>(x, out);
}